// round 4
// baseline (speedup 1.0000x reference)
#include <cuda_runtime.h>
#include <math.h>

#define NN 8
#define CC 80
#define HH 100
#define WW 152
#define PP 15200           // H*W
#define PCE 1216000        // C*P
#define NBINS 4096
#define CAP 8192
#define TOPK 1000
#define OUTK 100
#define ELEMS 32
#define PRE_TH 0.05f
#define NMS_TH 0.6f
#define COFF 100000.0f

// -------- static scratch (no allocations allowed) --------
__device__ float              g_ctr[NN * PP];
__device__ unsigned           g_hist[NN * NBINS];
__device__ int                g_cut[NN];
__device__ int                g_cnt[NN];
__device__ unsigned long long g_cand[NN * CAP];
__device__ float4             g_box[NN * TOPK];    // raw clipped boxes
__device__ float4             g_obox[NN * TOPK];   // class-offset boxes
__device__ float              g_area[NN * TOPK];   // area of offset boxes
__device__ float              g_sc[NN * TOPK];
__device__ int                g_lab[NN * TOPK];
__device__ int                g_nv[NN];
__device__ unsigned           g_mask[NN * TOPK * 32];

extern __shared__ unsigned long long dynsmem[];

__device__ __forceinline__ float sigm(float x) { return 1.0f / (1.0f + expf(-x)); }

// K0: zero hist/counters, precompute centerness sigmoid
__global__ void k_init(const float* __restrict__ ctr) {
    int i = blockIdx.x * blockDim.x + threadIdx.x;
    if (i < NN * PP)    g_ctr[i] = sigm(ctr[i]);
    if (i < NN * NBINS) g_hist[i] = 0u;
    if (i < NN)         g_cnt[i] = 0;
}

// K1: score histogram on float bits (4096 bins = bits[30:18])
__global__ void k_hist(const float* __restrict__ cls) {
    __shared__ unsigned sh[NBINS];
    int img = blockIdx.y;
    for (int b = threadIdx.x; b < NBINS; b += blockDim.x) sh[b] = 0u;
    __syncthreads();
    const float* c   = cls + (long)img * PCE;
    const float* ctr = g_ctr + img * PP;
    int base = blockIdx.x * (blockDim.x * ELEMS);
    for (int it = 0; it < ELEMS; it++) {
        int e = base + it * blockDim.x + threadIdx.x;
        if (e < PCE) {
            float sc_ = sigm(c[e]);
            if (sc_ > PRE_TH) {
                int p = e % PP;
                float s = sc_ * ctr[p];
                atomicAdd(&sh[__float_as_uint(s) >> 18], 1u);
            }
        }
    }
    __syncthreads();
    for (int b = threadIdx.x; b < NBINS; b += blockDim.x) {
        unsigned v = sh[b];
        if (v) atomicAdd(&g_hist[img * NBINS + b], v);
    }
}

// K2: suffix-scan histogram, find bin containing rank-1000 cutoff
__global__ void k_cut() {
    __shared__ unsigned s[NBINS];
    int img = blockIdx.x;
    int tid = threadIdx.x;  // 1024 threads, 4 bins each
    for (int b = tid; b < NBINS; b += 1024) s[b] = g_hist[img * NBINS + b];
    __syncthreads();
    for (int d = 1; d < NBINS; d <<= 1) {
        unsigned t0 = s[tid]        + ((tid + d        < NBINS) ? s[tid + d]        : 0u);
        unsigned t1 = s[tid + 1024] + ((tid + 1024 + d < NBINS) ? s[tid + 1024 + d] : 0u);
        unsigned t2 = s[tid + 2048] + ((tid + 2048 + d < NBINS) ? s[tid + 2048 + d] : 0u);
        unsigned t3 = s[tid + 3072] + ((tid + 3072 + d < NBINS) ? s[tid + 3072 + d] : 0u);
        __syncthreads();
        s[tid] = t0; s[tid + 1024] = t1; s[tid + 2048] = t2; s[tid + 3072] = t3;
        __syncthreads();
    }
    for (int q = 0; q < 4; q++) {
        int b = tid + q * 1024;
        if (s[b] >= TOPK && (b == NBINS - 1 || s[b + 1] < TOPK)) g_cut[img] = b;
    }
    if (tid == 0 && s[0] < TOPK) g_cut[img] = 0;
}

// K3: recompute scores, compact candidates in bins >= cut
__global__ void k_compact(const float* __restrict__ cls) {
    int img = blockIdx.y;
    int cut = g_cut[img];
    const float* c   = cls + (long)img * PCE;
    const float* ctr = g_ctr + img * PP;
    int base = blockIdx.x * (blockDim.x * ELEMS);
    for (int it = 0; it < ELEMS; it++) {
        int e = base + it * blockDim.x + threadIdx.x;
        if (e < PCE) {
            float sc_ = sigm(c[e]);
            if (sc_ > PRE_TH) {
                int p = e % PP;
                int ch = e / PP;
                float s = sc_ * ctr[p];
                unsigned u = __float_as_uint(s);
                if ((int)(u >> 18) >= cut) {
                    int pos = atomicAdd(&g_cnt[img], 1);
                    if (pos < CAP) {
                        unsigned idx = (unsigned)(p * CC + ch);  // flat index of [P,C]
                        g_cand[img * CAP + pos] =
                            ((unsigned long long)(~u) << 32) | (unsigned long long)idx;
                    }
                }
            }
        }
    }
}

// K4: bitonic sort candidates (score desc, idx asc), decode top-1000 boxes
__global__ void k_sort(const float* __restrict__ regs, const float* __restrict__ locs,
                       const float* __restrict__ info) {
    unsigned long long* sh = dynsmem;
    int img = blockIdx.x;
    int tid = threadIdx.x;  // 1024
    int n = g_cnt[img]; if (n > CAP) n = CAP;
    for (int t = tid; t < CAP; t += 1024)
        sh[t] = (t < n) ? g_cand[img * CAP + t] : ~0ULL;
    __syncthreads();
    int n2 = 1; while (n2 < n) n2 <<= 1;
    for (int k = 2; k <= n2; k <<= 1)
        for (int j = k >> 1; j > 0; j >>= 1) {
            for (int i = tid; i < n2; i += 1024) {
                int l = i ^ j;
                if (l > i) {
                    unsigned long long a = sh[i], b = sh[l];
                    bool asc = ((i & k) == 0);
                    if ((a > b) == asc) { sh[i] = b; sh[l] = a; }
                }
            }
            __syncthreads();
        }
    if (tid < TOPK) {
        int t = tid;
        bool valid = (t < n);
        float4 bx = make_float4(0.f, 0.f, 0.f, 0.f);
        float4 ob = make_float4(0.f, 0.f, 0.f, 0.f);
        float s = 0.f, ar = 0.f; int lab = 0;
        if (valid) {
            unsigned long long e = sh[t];
            unsigned u = ~((unsigned)(e >> 32));
            unsigned idx = (unsigned)e;
            s = __uint_as_float(u);
            int loc = (int)(idx / CC);
            lab = (int)(idx % CC) + 1;
            const float* rg = regs + (long)img * 4 * PP;
            float rl = rg[loc], rt = rg[PP + loc], rr = rg[2 * PP + loc], rb = rg[3 * PP + loc];
            float px = locs[2 * loc], py = locs[2 * loc + 1];
            float him = info[img * 2], wim = info[img * 2 + 1];
            float x1 = fminf(fmaxf(px - rl, 0.f), wim - 1.f);
            float y1 = fminf(fmaxf(py - rt, 0.f), him - 1.f);
            float x2 = fminf(fmaxf(px + rr, 0.f), wim - 1.f);
            float y2 = fminf(fmaxf(py + rb, 0.f), him - 1.f);
            bx = make_float4(x1, y1, x2, y2);
            float off = (float)lab * COFF;
            ob = make_float4(x1 + off, y1 + off, x2 + off, y2 + off);
            ar = fmaxf(ob.z - ob.x, 0.f) * fmaxf(ob.w - ob.y, 0.f);
        }
        g_box[img * TOPK + t]  = bx;
        g_obox[img * TOPK + t] = ob;
        g_area[img * TOPK + t] = ar;
        g_sc[img * TOPK + t]   = s;
        g_lab[img * TOPK + t]  = lab;
    }
    if (tid == 0) g_nv[img] = (n < TOPK) ? n : TOPK;
}

// K5: suppression bit-matrix (1000 rows x 32 words), reference-exact IoU on offset boxes
__global__ void k_iou() {
    __shared__ float4 sob[1024];
    __shared__ float  sar[1024];
    int img = blockIdx.y;
    for (int t = threadIdx.x; t < 1024; t += 256) {
        if (t < TOPK) { sob[t] = g_obox[img * TOPK + t]; sar[t] = g_area[img * TOPK + t]; }
        else          { sob[t] = make_float4(0.f, 0.f, 0.f, 0.f); sar[t] = 0.f; }
    }
    __syncthreads();
    int item = blockIdx.x * 256 + threadIdx.x;
    if (item >= TOPK * 32) return;
    int i = item >> 5, w = item & 31;
    float4 bi = sob[i]; float ai = sar[i];
    unsigned bits = 0u;
    int jbase = w * 32;
#pragma unroll
    for (int b = 0; b < 32; b++) {
        int j = jbase + b;
        if (j > i && j < TOPK) {
            float4 bj = sob[j];
            float lx = fmaxf(bi.x, bj.x), ly = fmaxf(bi.y, bj.y);
            float rx = fminf(bi.z, bj.z), ry = fminf(bi.w, bj.w);
            float iw = fmaxf(rx - lx, 0.f), ih = fmaxf(ry - ly, 0.f);
            float inter = iw * ih;
            float iou = inter / (ai + sar[j] - inter + 1e-9f);
            if (iou > NMS_TH) bits |= (1u << b);
        }
    }
    g_mask[(img * TOPK + i) * 32 + w] = bits;
}

// K6: warp-serial greedy NMS with early exit at 100 detections, emit output
__global__ void k_nms(float* __restrict__ out) {
    unsigned* smk = (unsigned*)dynsmem;  // TOPK*32 words
    __shared__ int skeep[OUTK];
    __shared__ int sfound;
    int img = blockIdx.x;
    int tid = threadIdx.x;  // 1024
    for (int t = tid; t < TOPK * 32; t += 1024) smk[t] = g_mask[img * TOPK * 32 + t];
    __syncthreads();
    if (tid < 32) {
        int lane = tid;
        int nv = g_nv[img];
        int lo = lane * 32;
        unsigned skip;
        if (lo >= nv)            skip = 0xFFFFFFFFu;
        else if (lo + 32 <= nv)  skip = 0u;
        else                     skip = 0xFFFFFFFFu << (nv - lo);
        int found = 0;
        for (int i = 0; i < TOPK; i++) {
            unsigned word = __shfl_sync(0xFFFFFFFFu, skip, i >> 5);
            if (!((word >> (i & 31)) & 1u)) {
                if (lane == 0) skeep[found] = i;
                found++;
                if (found >= OUTK) break;
                skip |= smk[i * 32 + lane];
            }
        }
        if (lane == 0) sfound = found;
    }
    __syncthreads();
    if (tid < OUTK * 6) {
        int r = tid / 6, k = tid % 6;
        float v = 0.f;
        if (r < sfound) {
            int i = skeep[r];
            if (k < 4)      v = ((const float*)g_box)[(img * TOPK + i) * 4 + k];
            else if (k == 4) v = (float)g_lab[img * TOPK + i];
            else            v = g_sc[img * TOPK + i];
        }
        out[img * OUTK * 6 + tid] = v;
    }
}

extern "C" void kernel_launch(void* const* d_in, const int* in_sizes, int n_in,
                              void* d_out, int out_size) {
    const float* locs = (const float*)d_in[0];   // [P,2]
    const float* cls  = (const float*)d_in[1];   // [N,C,H,W]
    const float* regs = (const float*)d_in[2];   // [N,4,H,W]
    const float* ctr  = (const float*)d_in[3];   // [N,1,H,W]
    const float* info = (const float*)d_in[4];   // [N,2]
    float* out = (float*)d_out;                  // [N,100,6]

    cudaFuncSetAttribute(k_sort, cudaFuncAttributeMaxDynamicSharedMemorySize, CAP * 8);
    cudaFuncSetAttribute(k_nms,  cudaFuncAttributeMaxDynamicSharedMemorySize, TOPK * 32 * 4);

    k_init<<<(NN * PP + 255) / 256, 256>>>(ctr);
    dim3 g1((PCE + 256 * ELEMS - 1) / (256 * ELEMS), NN);
    k_hist<<<g1, 256>>>(cls);
    k_cut<<<NN, 1024>>>();
    k_compact<<<g1, 256>>>(cls);
    k_sort<<<NN, 1024, CAP * 8>>>(regs, locs, info);
    k_iou<<<dim3((TOPK * 32 + 255) / 256, NN), 256>>>();
    k_nms<<<NN, 1024, TOPK * 32 * 4>>>(out);
}

// round 7
// speedup vs baseline: 1.1085x; 1.1085x over previous
#include <cuda_runtime.h>
#include <math.h>

#define NN 8
#define CC 80
#define HH 100
#define WW 152
#define PP 15200           // H*W
#define PCE 1216000        // C*P
#define PC4 (PCE/4)        // 304000
#define NBINS 4096
#define CAP 8192
#define TOPK 1000
#define OUTK 100
#define VEC_IT 8           // float4s per thread per pass
#define PRE_TH 0.05f
#define RAW_PRE_TH -2.95f  // conservative logit(0.05) = -2.944439
#define NMS_TH 0.6f
#define COFF 100000.0f

// -------- static scratch (no allocations allowed) --------
__device__ float              g_ctr[NN * PP];
__device__ unsigned           g_hist[NN * NBINS];
__device__ int                g_cut[NN];
__device__ float              g_thr[NN];
__device__ int                g_cnt[NN];
__device__ unsigned long long g_cand[NN * CAP];
__device__ float4             g_box[NN * TOPK];    // raw clipped boxes
__device__ float4             g_obox[NN * TOPK];   // class-offset boxes
__device__ float              g_area[NN * TOPK];   // area of offset boxes
__device__ float              g_sc[NN * TOPK];
__device__ int                g_lab[NN * TOPK];
__device__ int                g_nv[NN];
__device__ unsigned           g_mask[NN * TOPK * 32];

extern __shared__ unsigned long long dynsmem[];

__device__ __forceinline__ float sigm_exact(float x) { return 1.0f / (1.0f + expf(-x)); }
__device__ __forceinline__ float sigm_fast(float x)  { return __fdividef(1.0f, 1.0f + __expf(-x)); }

// K0: zero hist/counters, precompute EXACT centerness sigmoid (reused 80x per point)
__global__ void k_init(const float* __restrict__ ctr) {
    int i = blockIdx.x * blockDim.x + threadIdx.x;
    if (i < NN * PP)    g_ctr[i] = sigm_exact(ctr[i]);
    if (i < NN * NBINS) g_hist[i] = 0u;
    if (i < NN)         g_cnt[i] = 0;
}

// K1: approximate score histogram (fast sigmoid; bin granularity absorbs the error)
__global__ void k_hist(const float4* __restrict__ cls4) {
    __shared__ unsigned sh[NBINS];
    int img = blockIdx.y;
    for (int b = threadIdx.x; b < NBINS; b += blockDim.x) sh[b] = 0u;
    __syncthreads();
    const float4* c4  = cls4 + (long)img * PC4;
    const float*  ctr = g_ctr + img * PP;
    int base = blockIdx.x * (blockDim.x * VEC_IT);
    for (int it = 0; it < VEC_IT; it++) {
        int q = base + it * blockDim.x + threadIdx.x;
        if (q < PC4) {
            float4 v = c4[q];
            int p0 = (q * 4) % PP;   // PP%4==0 -> all 4 lanes same channel, p = p0+l
            float vs[4] = {v.x, v.y, v.z, v.w};
#pragma unroll
            for (int l = 0; l < 4; l++) {
                float c = vs[l];
                if (c > RAW_PRE_TH) {
                    float sc = sigm_fast(c);
                    if (sc > PRE_TH) {
                        float s = sc * ctr[p0 + l];
                        atomicAdd(&sh[__float_as_uint(s) >> 18], 1u);
                    }
                }
            }
        }
    }
    __syncthreads();
    for (int b = threadIdx.x; b < NBINS; b += blockDim.x) {
        unsigned v = sh[b];
        if (v) atomicAdd(&g_hist[img * NBINS + b], v);
    }
}

// K2: suffix-scan histogram; pick cut bin with 1-bin safety margin; derive raw-logit prefilter
__global__ void k_cut() {
    __shared__ unsigned s[NBINS];
    __shared__ int scut;
    int img = blockIdx.x;
    int tid = threadIdx.x;  // 1024 threads, 4 bins each
    for (int b = tid; b < NBINS; b += 1024) s[b] = g_hist[img * NBINS + b];
    __syncthreads();
    for (int d = 1; d < NBINS; d <<= 1) {
        unsigned t0 = s[tid]        + ((tid + d        < NBINS) ? s[tid + d]        : 0u);
        unsigned t1 = s[tid + 1024] + ((tid + 1024 + d < NBINS) ? s[tid + 1024 + d] : 0u);
        unsigned t2 = s[tid + 2048] + ((tid + 2048 + d < NBINS) ? s[tid + 2048 + d] : 0u);
        unsigned t3 = s[tid + 3072] + ((tid + 3072 + d < NBINS) ? s[tid + 3072 + d] : 0u);
        __syncthreads();
        s[tid] = t0; s[tid + 1024] = t1; s[tid + 2048] = t2; s[tid + 3072] = t3;
        __syncthreads();
    }
    // s[b] = count of candidates with (approx) score-bin >= b
    for (int q = 0; q < 4; q++) {
        int b = tid + q * 1024;
        if (s[b] >= TOPK && (b == NBINS - 1 || s[b + 1] < TOPK)) scut = b;
    }
    if (tid == 0 && s[0] < TOPK) scut = 0;
    __syncthreads();
    if (tid == 0) {
        int cut = scut;
        int cut_eff = (cut > 0) ? cut - 1 : 0;               // 1-bin margin for fast-sigmoid error
        if (cut_eff < cut && s[cut_eff] > CAP - 1024) cut_eff = cut;  // don't overflow CAP
        g_cut[img] = cut_eff;
        float thr = RAW_PRE_TH;
        if (cut_eff > 0) {
            float s_lo = __uint_as_float((unsigned)cut_eff << 18);    // lower edge of cut bin
            if (s_lo > 0.0f && s_lo < 1.0f) {
                // score <= sigmoid(cls); cls < logit(s_lo) cannot reach bin cut_eff
                float t = logf(s_lo / (1.0f - s_lo)) - 1e-3f;         // small safety margin
                thr = fmaxf(t, RAW_PRE_TH);
            }
        }
        g_thr[img] = thr;
    }
}

// K3: streaming raw-logit prefilter; exact sigmoid only for the few survivors
__global__ void k_compact(const float4* __restrict__ cls4) {
    int img = blockIdx.y;
    int cut = g_cut[img];
    float thr = g_thr[img];
    const float4* c4  = cls4 + (long)img * PC4;
    const float*  ctr = g_ctr + img * PP;
    int base = blockIdx.x * (blockDim.x * VEC_IT);
    for (int it = 0; it < VEC_IT; it++) {
        int q = base + it * blockDim.x + threadIdx.x;
        if (q < PC4) {
            float4 v = c4[q];
            int e0 = q * 4;
            int p0 = e0 % PP;
            int ch = e0 / PP;
            float vs[4] = {v.x, v.y, v.z, v.w};
#pragma unroll
            for (int l = 0; l < 4; l++) {
                float c = vs[l];
                if (c > thr) {
                    float sc = sigm_exact(c);                 // exact: defines final ordering
                    if (sc > PRE_TH) {
                        float s = sc * ctr[p0 + l];
                        unsigned u = __float_as_uint(s);
                        if ((int)(u >> 18) >= cut) {
                            int pos = atomicAdd(&g_cnt[img], 1);
                            if (pos < CAP) {
                                unsigned idx = (unsigned)((p0 + l) * CC + ch);  // flat [P,C] index
                                g_cand[img * CAP + pos] =
                                    ((unsigned long long)(~u) << 32) | (unsigned long long)idx;
                            }
                        }
                    }
                }
            }
        }
    }
}

// K4: bitonic sort candidates (score desc, idx asc), decode top-1000 boxes
__global__ void k_sort(const float* __restrict__ regs, const float* __restrict__ locs,
                       const float* __restrict__ info) {
    unsigned long long* sh = dynsmem;
    int img = blockIdx.x;
    int tid = threadIdx.x;  // 1024
    int n = g_cnt[img]; if (n > CAP) n = CAP;
    for (int t = tid; t < CAP; t += 1024)
        sh[t] = (t < n) ? g_cand[img * CAP + t] : ~0ULL;
    __syncthreads();
    int n2 = 1; while (n2 < n) n2 <<= 1;
    for (int k = 2; k <= n2; k <<= 1)
        for (int j = k >> 1; j > 0; j >>= 1) {
            for (int i = tid; i < n2; i += 1024) {
                int l = i ^ j;
                if (l > i) {
                    unsigned long long a = sh[i], b = sh[l];
                    bool asc = ((i & k) == 0);
                    if ((a > b) == asc) { sh[i] = b; sh[l] = a; }
                }
            }
            __syncthreads();
        }
    if (tid < TOPK) {
        int t = tid;
        bool valid = (t < n);
        float4 bx = make_float4(0.f, 0.f, 0.f, 0.f);
        float4 ob = make_float4(0.f, 0.f, 0.f, 0.f);
        float s = 0.f, ar = 0.f; int lab = 0;
        if (valid) {
            unsigned long long e = sh[t];
            unsigned u = ~((unsigned)(e >> 32));
            unsigned idx = (unsigned)e;
            s = __uint_as_float(u);
            int loc = (int)(idx / CC);
            lab = (int)(idx % CC) + 1;
            const float* rg = regs + (long)img * 4 * PP;
            float rl = rg[loc], rt = rg[PP + loc], rr = rg[2 * PP + loc], rb = rg[3 * PP + loc];
            float px = locs[2 * loc], py = locs[2 * loc + 1];
            float him = info[img * 2], wim = info[img * 2 + 1];
            float x1 = fminf(fmaxf(px - rl, 0.f), wim - 1.f);
            float y1 = fminf(fmaxf(py - rt, 0.f), him - 1.f);
            float x2 = fminf(fmaxf(px + rr, 0.f), wim - 1.f);
            float y2 = fminf(fmaxf(py + rb, 0.f), him - 1.f);
            bx = make_float4(x1, y1, x2, y2);
            float off = (float)lab * COFF;
            ob = make_float4(x1 + off, y1 + off, x2 + off, y2 + off);
            ar = fmaxf(ob.z - ob.x, 0.f) * fmaxf(ob.w - ob.y, 0.f);
        }
        g_box[img * TOPK + t]  = bx;
        g_obox[img * TOPK + t] = ob;
        g_area[img * TOPK + t] = ar;
        g_sc[img * TOPK + t]   = s;
        g_lab[img * TOPK + t]  = lab;
    }
    if (tid == 0) g_nv[img] = (n < TOPK) ? n : TOPK;
}

// K5: suppression bit-matrix (1000 rows x 32 words), reference-exact IoU on offset boxes
__global__ void k_iou() {
    __shared__ float4 sob[1024];
    __shared__ float  sar[1024];
    int img = blockIdx.y;
    for (int t = threadIdx.x; t < 1024; t += 256) {
        if (t < TOPK) { sob[t] = g_obox[img * TOPK + t]; sar[t] = g_area[img * TOPK + t]; }
        else          { sob[t] = make_float4(0.f, 0.f, 0.f, 0.f); sar[t] = 0.f; }
    }
    __syncthreads();
    int item = blockIdx.x * 256 + threadIdx.x;
    if (item >= TOPK * 32) return;
    int i = item >> 5, w = item & 31;
    float4 bi = sob[i]; float ai = sar[i];
    unsigned bits = 0u;
    int jbase = w * 32;
#pragma unroll
    for (int b = 0; b < 32; b++) {
        int j = jbase + b;
        if (j > i && j < TOPK) {
            float4 bj = sob[j];
            float lx = fmaxf(bi.x, bj.x), ly = fmaxf(bi.y, bj.y);
            float rx = fminf(bi.z, bj.z), ry = fminf(bi.w, bj.w);
            float iw = fmaxf(rx - lx, 0.f), ih = fmaxf(ry - ly, 0.f);
            float inter = iw * ih;
            float iou = inter / (ai + sar[j] - inter + 1e-9f);
            if (iou > NMS_TH) bits |= (1u << b);
        }
    }
    g_mask[(img * TOPK + i) * 32 + w] = bits;
}

// K6: warp-serial greedy NMS with early exit at 100 detections, emit output
__global__ void k_nms(float* __restrict__ out) {
    unsigned* smk = (unsigned*)dynsmem;  // TOPK*32 words
    __shared__ int skeep[OUTK];
    __shared__ int sfound;
    int img = blockIdx.x;
    int tid = threadIdx.x;  // 1024
    for (int t = tid; t < TOPK * 32; t += 1024) smk[t] = g_mask[img * TOPK * 32 + t];
    __syncthreads();
    if (tid < 32) {
        int lane = tid;
        int nv = g_nv[img];
        int lo = lane * 32;
        unsigned skip;
        if (lo >= nv)            skip = 0xFFFFFFFFu;
        else if (lo + 32 <= nv)  skip = 0u;
        else                     skip = 0xFFFFFFFFu << (nv - lo);
        int found = 0;
        for (int i = 0; i < TOPK; i++) {
            unsigned word = __shfl_sync(0xFFFFFFFFu, skip, i >> 5);
            if (!((word >> (i & 31)) & 1u)) {
                if (lane == 0) skeep[found] = i;
                found++;
                if (found >= OUTK) break;
                skip |= smk[i * 32 + lane];
            }
        }
        if (lane == 0) sfound = found;
    }
    __syncthreads();
    if (tid < OUTK * 6) {
        int r = tid / 6, k = tid % 6;
        float v = 0.f;
        if (r < sfound) {
            int i = skeep[r];
            if (k < 4)      v = ((const float*)g_box)[(img * TOPK + i) * 4 + k];
            else if (k == 4) v = (float)g_lab[img * TOPK + i];
            else            v = g_sc[img * TOPK + i];
        }
        out[img * OUTK * 6 + tid] = v;
    }
}

extern "C" void kernel_launch(void* const* d_in, const int* in_sizes, int n_in,
                              void* d_out, int out_size) {
    const float* locs = (const float*)d_in[0];   // [P,2]
    const float* cls  = (const float*)d_in[1];   // [N,C,H,W]
    const float* regs = (const float*)d_in[2];   // [N,4,H,W]
    const float* ctr  = (const float*)d_in[3];   // [N,1,H,W]
    const float* info = (const float*)d_in[4];   // [N,2]
    float* out = (float*)d_out;                  // [N,100,6]

    cudaFuncSetAttribute(k_sort, cudaFuncAttributeMaxDynamicSharedMemorySize, CAP * 8);
    cudaFuncSetAttribute(k_nms,  cudaFuncAttributeMaxDynamicSharedMemorySize, TOPK * 32 * 4);

    k_init<<<(NN * PP + 255) / 256, 256>>>(ctr);
    dim3 g1((PC4 + 256 * VEC_IT - 1) / (256 * VEC_IT), NN);
    k_hist<<<g1, 256>>>((const float4*)cls);
    k_cut<<<NN, 1024>>>();
    k_compact<<<g1, 256>>>((const float4*)cls);
    k_sort<<<NN, 1024, CAP * 8>>>(regs, locs, info);
    k_iou<<<dim3((TOPK * 32 + 255) / 256, NN), 256>>>();
    k_nms<<<NN, 1024, TOPK * 32 * 4>>>(out);
}